// round 10
// baseline (speedup 1.0000x reference)
#include <cuda_runtime.h>
#include <cuda_bf16.h>
#include <cstdint>

// ---------------------------------------------------------------------------
// Scratch (static __device__ arrays; no allocation allowed)
// ---------------------------------------------------------------------------
__device__ float g_bufA[32u * 768u * 512u];                    // conv5 fp32 out
__device__ __nv_bfloat16 g_wsplit[3u * 768u * 3072u];          // [p][co][KPAD]
__device__ __nv_bfloat16 g_xsA[3u * 3u * 32u * 768u * 1024u];  // plane ping (453MB)
__device__ __nv_bfloat16 g_xsB[3u * 3u * 32u * 768u * 1024u];  // plane pong (453MB)
__device__ float g_w6t[768u * 64u];
__device__ float g_z[32u * 511u * 64u];
__device__ float g_enorm[512];
__device__ float g_counts[512];
__device__ float g_loss[1];

// ---------------------------------------------------------------------------
// Helpers (baseline PTX only — compute_103-safe)
// ---------------------------------------------------------------------------
__device__ __forceinline__ uint32_t smem_u32(const void* p) {
    uint32_t a;
    asm("{ .reg .u64 t; cvta.to.shared.u64 t, %1; cvt.u32.u64 %0, t; }"
        : "=r"(a) : "l"(p));
    return a;
}

#define LDSM4(r0, r1, r2, r3, addr)                                              \
    asm volatile("ldmatrix.sync.aligned.m8n8.x4.shared.b16 {%0,%1,%2,%3}, [%4];" \
                 : "=r"(r0), "=r"(r1), "=r"(r2), "=r"(r3) : "r"(addr))

#define LDSM4T(r0, r1, r2, r3, addr)                                             \
    asm volatile("ldmatrix.sync.aligned.m8n8.x4.trans.shared.b16 {%0,%1,%2,%3}, [%4];" \
                 : "=r"(r0), "=r"(r1), "=r"(r2), "=r"(r3) : "r"(addr))

#define MMA16816(c, a, b0, b1)                                                   \
    asm volatile(                                                                \
        "mma.sync.aligned.m16n8k16.row.col.f32.bf16.bf16.f32 "                   \
        "{%0,%1,%2,%3}, {%4,%5,%6,%7}, {%8,%9}, {%0,%1,%2,%3};"                  \
        : "+f"((c)[0]), "+f"((c)[1]), "+f"((c)[2]), "+f"((c)[3])                 \
        : "r"((a)[0]), "r"((a)[1]), "r"((a)[2]), "r"((a)[3]),                    \
          "r"(b0), "r"(b1))

#define CP_ASYNC16(dst, src, sz)                                                 \
    asm volatile("cp.async.cg.shared.global [%0], [%1], 16, %2;"                 \
                 :: "r"(dst), "l"(src), "r"(sz) : "memory")
#define CP_COMMIT() asm volatile("cp.async.commit_group;" ::: "memory")
#define CP_WAIT0() asm volatile("cp.async.wait_group 0;" ::: "memory")

__device__ __forceinline__ void split3(float v, unsigned short& h,
                                       unsigned short& m, unsigned short& l) {
    __nv_bfloat16 bh = __float2bfloat16(v);
    float fh = __bfloat162float(bh);
    __nv_bfloat16 bm = __float2bfloat16(v - fh);
    float fm = __bfloat162float(bm);
    __nv_bfloat16 bl = __float2bfloat16(v - fh - fm);
    h = __bfloat16_as_ushort(bh);
    m = __bfloat16_as_ushort(bm);
    l = __bfloat16_as_ushort(bl);
}

// ---------------------------------------------------------------------------
// Weight split: w[co][ci][tap] fp32 -> 3 bf16 planes [p][co][KPAD]
// ---------------------------------------------------------------------------
__global__ void split_w_kernel(const float* __restrict__ w,
                               __nv_bfloat16* __restrict__ w3,
                               int CIN, int KS, int KPAD) {
    int idx = blockIdx.x * 256 + threadIdx.x;
    int total = 768 * KPAD;
    if (idx >= total) return;
    int k = idx % KPAD;
    int co = idx / KPAD;
    float v = (k < CIN * KS) ? w[(size_t)co * CIN * KS + k] : 0.0f;
    unsigned short h, m, l;
    split3(v, h, m, l);
    w3[idx] = __ushort_as_bfloat16(h);
    w3[total + idx] = __ushort_as_bfloat16(m);
    w3[2 * total + idx] = __ushort_as_bfloat16(l);
}

// ---------------------------------------------------------------------------
// Activation split + tap-expand for LAYER 1 input only (mels fp32 -> planes)
// ---------------------------------------------------------------------------
__global__ void xsplit_kernel(const float* __restrict__ x,
                              __nv_bfloat16* __restrict__ xs,
                              int CIN, int T_in, int TS_in, int TSo,
                              int S, int PAD, int KS, int total) {
    int idx = blockIdx.x * 256 + threadIdx.x;
    if (idx >= total) return;
    const int th = TSo >> 1;
    int t2 = idx % th;
    int r = idx / th;
    int ci = r % CIN;
    r /= CIN;
    int bb = r & 31;
    int tap = r >> 5;
    const float* xr = x + ((size_t)bb * CIN + ci) * TS_in;

    unsigned short hb[2], mb[2], lb[2];
#pragma unroll
    for (int j = 0; j < 2; ++j) {
        int t = 2 * t2 + j;
        int tin = t * S + tap - PAD;
        float v = (tin >= 0 && tin < T_in) ? xr[tin] : 0.0f;
        split3(v, hb[j], mb[j], lb[j]);
    }
    size_t pstride = (size_t)KS * 32 * CIN * TSo;
    size_t o = (((size_t)tap * 32 + bb) * CIN + ci) * TSo + 2 * t2;
    *(uint32_t*)(xs + o) = (uint32_t)hb[0] | ((uint32_t)hb[1] << 16);
    *(uint32_t*)(xs + o + pstride) = (uint32_t)mb[0] | ((uint32_t)mb[1] << 16);
    *(uint32_t*)(xs + o + 2 * pstride) = (uint32_t)lb[0] | ((uint32_t)lb[1] << 16);
}

// ---------------------------------------------------------------------------
// Zero boundary strips of a plane buffer: slots whose source index is out of
// range (x[<0] or x[>=Tin]) must be zero; conv epilogue never writes them.
// Covers first 3 and last 5 t' columns (sufficient for all layer geometries).
// ---------------------------------------------------------------------------
__global__ void strip_kernel(__nv_bfloat16* __restrict__ xs, int KS, int S,
                             int PAD, int Tin, int TSo, int total) {
    int idx = blockIdx.x * 256 + threadIdx.x;
    if (idx >= total) return;
    int c = idx & 7;
    int r = idx >> 3;
    int ci = r % 768;
    r /= 768;
    int bb = r & 31;
    r >>= 5;
    int tap = r % KS;
    int p = r / KS;
    int tp = (c < 3) ? c : TSo - 8 + c;
    int tin = tp * S + tap - PAD;
    if (tin < 0 || tin >= Tin) {
        size_t ps = (size_t)KS * 32 * 768 * TSo;
        xs[(size_t)p * ps + (((size_t)tap * 32 + bb) * 768 + ci) * TSo + tp] =
            __ushort_as_bfloat16((unsigned short)0);
    }
}

// ---------------------------------------------------------------------------
// Conv + BN + ReLU: bf16 mma.sync, 3-way split (6 products), cp.async fill.
// Block tile 128co x 128t, 8 warps (64x32 each), K-chunks of 32, double buffer.
// Epilogue OUTMODE 0: fused split+tap-expand writes next layer's bf16 planes.
//          OUTMODE 1: plain fp32 (for conv6 input).
// ---------------------------------------------------------------------------
template <int CIN, int KS, int NKS, int NS, int OUTMODE>
__global__ void __launch_bounds__(256, 2)
conv_mma_kernel(const __nv_bfloat16* __restrict__ xs,
                const __nv_bfloat16* __restrict__ w3,
                const float* __restrict__ gamma, const float* __restrict__ beta,
                const float* __restrict__ mean, const float* __restrict__ var,
                float* __restrict__ outf, __nv_bfloat16* __restrict__ xsn,
                int TSo, int T_out, int TSoN) {
    constexpr int KTOT = CIN * KS;
    constexpr int KPAD = ((KTOT + 31) / 32) * 32;
    constexpr int NCH = KPAD / 32;
    constexpr uint32_t BUFSZ = 6 * 8192;

    extern __shared__ __align__(16) char smem[];
    float* sInv = (float*)smem;
    float* sBb = (float*)(smem + 512);
    const uint32_t tilesBase = smem_u32(smem + 1024);

    const int b = blockIdx.z;
    const int co0 = blockIdx.y * 128;
    const int t0 = blockIdx.x * 128;
    const int tid = threadIdx.x;
    const int lane = tid & 31;
    const int warp = tid >> 5;
    const int wm = warp & 1;
    const int wn = warp >> 1;
    const int q = lane >> 3;
    const int r8 = lane & 7;

    if (tid < 128) {
        int co = co0 + tid;
        float iv = gamma[co] * rsqrtf(var[co] + 1e-5f);
        sInv[tid] = iv;
        sBb[tid] = beta[co] - mean[co] * iv;
    }

    float acc[4][4][4];
#pragma unroll
    for (int mb = 0; mb < 4; ++mb)
#pragma unroll
        for (int nb = 0; nb < 4; ++nb)
#pragma unroll
            for (int e = 0; e < 4; ++e) acc[mb][nb][e] = 0.0f;

    const size_t pstride = (size_t)KS * 32 * CIN * TSo;

    auto fill = [&](int c, uint32_t bsel) {
        const uint32_t tb = tilesBase + bsel * BUFSZ;
#pragma unroll
        for (int i = 0; i < 6; ++i) {
            int task = tid + i * 256;
            int g = task & 3;
            int row = (task >> 2) & 127;
            int p = task >> 9;
            uint32_t dst = tb + p * 8192 + (row << 6) + (((g + (row >> 1)) & 3) << 4);
            const __nv_bfloat16* src =
                w3 + ((size_t)(p * 768 + co0 + row)) * KPAD + c * 32 + g * 8;
            CP_ASYNC16(dst, src, 16);
        }
#pragma unroll
        for (int i = 0; i < 6; ++i) {
            int task = tid + i * 256;
            int tg = task & 15;
            int k = (task >> 4) & 31;
            int p = task >> 9;
            int kg = c * 32 + k;
            int ci = kg / KS;
            int tap = kg - ci * KS;
            const __nv_bfloat16* src =
                xs + (size_t)p * pstride +
                (((size_t)tap * 32 + b) * CIN + ci) * TSo + t0 + tg * 8;
            uint32_t dst = tb + 24576 + p * 8192 + (k << 8) + ((tg ^ (k & 7)) << 4);
            int sz = (kg < KTOT) ? 16 : 0;
            CP_ASYNC16(dst, src, sz);
        }
        CP_COMMIT();
    };

    fill(0, 0);

#pragma unroll 1
    for (int c = 0; c < NCH; ++c) {
        CP_WAIT0();
        __syncthreads();
        if (c + 1 < NCH) fill(c + 1, (c + 1) & 1);
        const uint32_t tb = tilesBase + (uint32_t)(c & 1) * BUFSZ;

#pragma unroll
        for (int ks = 0; ks < 2; ++ks) {
            uint32_t bfr[3][4][2];
#pragma unroll
            for (int p = 0; p < 3; ++p) {
#pragma unroll
                for (int jj = 0; jj < 2; ++jj) {
                    uint32_t k = ks * 16 + (q & 1) * 8 + r8;
                    uint32_t tg = wn * 4 + 2 * jj + (q >> 1);
                    uint32_t ad = tb + 24576 + p * 8192 + (k << 8) +
                                  ((tg ^ (k & 7)) << 4);
                    LDSM4T(bfr[p][2 * jj][0], bfr[p][2 * jj][1],
                           bfr[p][2 * jj + 1][0], bfr[p][2 * jj + 1][1], ad);
                }
            }
#pragma unroll
            for (int pa = 0; pa < 3; ++pa) {
                uint32_t a[4][4];
#pragma unroll
                for (int mb = 0; mb < 4; ++mb) {
                    uint32_t row = wm * 64 + mb * 16 + (q & 1) * 8 + r8;
                    uint32_t g = ks * 2 + (q >> 1);
                    uint32_t ad = tb + pa * 8192 + (row << 6) +
                                  (((g + (row >> 1)) & 3) << 4);
                    LDSM4(a[mb][0], a[mb][1], a[mb][2], a[mb][3], ad);
                }
#pragma unroll
                for (int pb = 0; pb < 3 - pa; ++pb)
#pragma unroll
                    for (int mb = 0; mb < 4; ++mb)
#pragma unroll
                        for (int nb = 0; nb < 4; ++nb)
                            MMA16816(acc[mb][nb], a[mb], bfr[pb][nb][0],
                                     bfr[pb][nb][1]);
            }
        }
    }

    // ---- Epilogue ----
    const size_t psN = (size_t)NKS * 32 * 768 * TSoN;  // next-plane stride (elems)
    unsigned short* xp = (unsigned short*)xsn;
    const int colb = t0 + wn * 32 + (lane & 3) * 2;

    // one value -> planes, stride-1 next layer (pair-capable done by caller)
    auto storeS2 = [&](float v, int r, int cc) {
        if (cc >= T_out) return;
        unsigned short h, m, l;
        split3(v, h, m, l);
        int tap0 = (cc + 1) & 1;
#pragma unroll
        for (int u = 0; u < 2; ++u) {
            int tap = tap0 + 2 * u;
            int tp = (cc + 1 - tap) >> 1;
            if (tp >= 0 && tp < TSoN) {
                size_t o = (((size_t)tap * 32 + b) * 768 + r) * TSoN + tp;
                xp[o] = h;
                xp[o + psN] = m;
                xp[o + 2 * psN] = l;
            }
        }
    };

    auto storeS1pair = [&](float v0, float v1, int r, int cc) {
        unsigned short h0, m0, l0, h1, m1, l1;
        split3(v0, h0, m0, l0);
        split3(v1, h1, m1, l1);
        bool s0 = (cc < T_out), s1 = (cc + 1 < T_out);
#pragma unroll
        for (int tap = 0; tap < 3; ++tap) {
            int tp = cc + 1 - tap;
            size_t o = (((size_t)tap * 32 + b) * 768 + r) * TSoN + tp;
            bool v0ok = s0 && tp >= 0 && tp < TSoN;
            bool v1ok = s1 && (tp + 1) >= 0 && (tp + 1) < TSoN;
            if (v0ok && v1ok && !(tp & 1)) {
                *(ushort2*)(xp + o) = make_ushort2(h0, h1);
                *(ushort2*)(xp + o + psN) = make_ushort2(m0, m1);
                *(ushort2*)(xp + o + 2 * psN) = make_ushort2(l0, l1);
            } else {
                if (v0ok) { xp[o] = h0; xp[o + psN] = m0; xp[o + 2 * psN] = l0; }
                if (v1ok) {
                    xp[o + 1] = h1;
                    xp[o + psN + 1] = m1;
                    xp[o + 2 * psN + 1] = l1;
                }
            }
        }
    };

#pragma unroll
    for (int mb = 0; mb < 4; ++mb) {
        const int row0 = wm * 64 + mb * 16 + (lane >> 2);
        const float i0 = sInv[row0], b0 = sBb[row0];
        const float i1 = sInv[row0 + 8], b1 = sBb[row0 + 8];
        const int r0g = co0 + row0;
#pragma unroll
        for (int nb = 0; nb < 4; ++nb) {
            const int cc = colb + nb * 8;
            float x0 = fmaxf(acc[mb][nb][0] * i0 + b0, 0.0f);
            float x1 = fmaxf(acc[mb][nb][1] * i0 + b0, 0.0f);
            float y0 = fmaxf(acc[mb][nb][2] * i1 + b1, 0.0f);
            float y1 = fmaxf(acc[mb][nb][3] * i1 + b1, 0.0f);
            if (OUTMODE == 1) {
                float* o0 = outf + ((size_t)b * 768 + r0g) * TSo + cc;
                *(float2*)o0 = make_float2(x0, x1);
                *(float2*)(o0 + (size_t)8 * TSo) = make_float2(y0, y1);
            } else if (NS == 1) {
                storeS1pair(x0, x1, r0g, cc);
                storeS1pair(y0, y1, r0g + 8, cc);
            } else {
                storeS2(x0, r0g, cc);
                storeS2(x1, r0g, cc + 1);
                storeS2(y0, r0g + 8, cc);
                storeS2(y1, r0g + 8, cc + 1);
            }
        }
    }
}

// ---------------------------------------------------------------------------
// 1x1 conv (w6) + bias + transpose to [B][T'][D]
// ---------------------------------------------------------------------------
__global__ void transpose_w6_kernel(const float* __restrict__ w6,
                                    float* __restrict__ w6t) {
    int idx = blockIdx.x * 256 + threadIdx.x;
    if (idx >= 768 * 64) return;
    int d = idx & 63;
    int ci = idx >> 6;
    w6t[idx] = w6[(size_t)d * 768 + ci];
}

__global__ void conv6_kernel(const float* __restrict__ x,
                             const float* __restrict__ w6t,
                             const float* __restrict__ b6,
                             float* __restrict__ z) {
    __shared__ float xsm[8][768];
    __shared__ float ws[64][64];
    const int b = blockIdx.y;
    const int t0 = blockIdx.x * 8;
    const int tid = threadIdx.x;

    for (int idx = tid; idx < 8 * 768; idx += 512) {
        int ci = idx >> 3, tl = idx & 7;
        int t = t0 + tl;
        xsm[tl][ci] = (t < 511) ? x[((size_t)b * 768 + ci) * 512 + t] : 0.0f;
    }
    const int tl = tid >> 6;
    const int d = tid & 63;
    float acc = 0.0f;
    for (int c0 = 0; c0 < 768; c0 += 64) {
        __syncthreads();
        for (int idx = tid; idx < 64 * 64; idx += 512) {
            int cc = idx >> 6, dd = idx & 63;
            ws[cc][dd] = w6t[(size_t)(c0 + cc) * 64 + dd];
        }
        __syncthreads();
#pragma unroll
        for (int cc = 0; cc < 64; ++cc) acc = fmaf(xsm[tl][c0 + cc], ws[cc][d], acc);
    }
    int t = t0 + tl;
    if (t < 511) z[((size_t)b * 511 + t) * 64 + d] = acc + b6[d];
}

// ---------------------------------------------------------------------------
// VQ
// ---------------------------------------------------------------------------
__global__ void vq_init_kernel(const float* __restrict__ emb,
                               float* __restrict__ enorm,
                               float* __restrict__ counts,
                               float* __restrict__ loss) {
    int c = threadIdx.x;
    float s = 0.0f;
#pragma unroll
    for (int dd = 0; dd < 64; ++dd) {
        float e = emb[(size_t)c * 64 + dd];
        s = fmaf(e, e, s);
    }
    enorm[c] = s;
    counts[c] = 0.0f;
    if (c == 0) loss[0] = 0.0f;
}

__global__ void vq_kernel(const float* __restrict__ z,
                          const float* __restrict__ emb,
                          const float* __restrict__ enorm,
                          float* __restrict__ out,
                          float* __restrict__ loss,
                          float* __restrict__ counts) {
    __shared__ __align__(16) float sE[128 * 64];
    __shared__ float sN[128];
    __shared__ float red[128];
    const int tid = threadIdx.x;
    const int row = blockIdx.x * 128 + tid;
    const bool valid = row < 16352;

    float zr[64];
    if (valid) {
#pragma unroll
        for (int k = 0; k < 16; ++k)
            *(float4*)&zr[k * 4] = *(const float4*)&z[(size_t)row * 64 + k * 4];
    } else {
#pragma unroll
        for (int k = 0; k < 64; ++k) zr[k] = 0.0f;
    }

    float best = 3.4e38f;
    int bi = 0;
    for (int c0 = 0; c0 < 512; c0 += 128) {
        __syncthreads();
        for (int k = tid; k < 2048; k += 128)
            ((float4*)sE)[k] = ((const float4*)(emb + (size_t)c0 * 64))[k];
        sN[tid] = enorm[c0 + tid];
        __syncthreads();
        const float4* sE4 = (const float4*)sE;
        for (int c = 0; c < 128; ++c) {
            float d0 = 0.0f, d1 = 0.0f, d2 = 0.0f, d3 = 0.0f;
#pragma unroll
            for (int k = 0; k < 16; ++k) {
                float4 e = sE4[c * 16 + k];
                d0 = fmaf(zr[4 * k + 0], e.x, d0);
                d1 = fmaf(zr[4 * k + 1], e.y, d1);
                d2 = fmaf(zr[4 * k + 2], e.z, d2);
                d3 = fmaf(zr[4 * k + 3], e.w, d3);
            }
            float dot = (d0 + d1) + (d2 + d3);
            float dist = fmaf(-2.0f, dot, sN[c]);
            if (dist < best) { best = dist; bi = c0 + c; }
        }
    }

    float diff2 = 0.0f;
    if (valid) {
        const float* e = emb + (size_t)bi * 64;
#pragma unroll
        for (int dd = 0; dd < 64; ++dd) {
            float ev = e[dd];
            out[(size_t)row * 64 + dd] = ev;
            float df = zr[dd] - ev;
            diff2 = fmaf(df, df, diff2);
        }
        atomicAdd(&counts[bi], 1.0f);
    }
    red[tid] = diff2;
    __syncthreads();
    for (int s = 64; s > 0; s >>= 1) {
        if (tid < s) red[tid] += red[tid + s];
        __syncthreads();
    }
    if (tid == 0) atomicAdd(loss, red[0]);
}

__global__ void vq_final_kernel(const float* __restrict__ counts,
                                const float* __restrict__ loss,
                                float* __restrict__ out) {
    __shared__ float red[512];
    int tid = threadIdx.x;
    float avg = counts[tid] * (1.0f / 16352.0f);
    red[tid] = avg * logf(avg + 1e-10f);
    __syncthreads();
    for (int s = 256; s > 0; s >>= 1) {
        if (tid < s) red[tid] += red[tid + s];
        __syncthreads();
    }
    if (tid == 0) {
        out[1046528] = 0.25f * loss[0] * (1.0f / 1046528.0f);
        out[1046529] = expf(-red[0]);
    }
}

// ---------------------------------------------------------------------------
// kernel_launch
// ---------------------------------------------------------------------------
extern "C" void kernel_launch(void* const* d_in, const int* in_sizes, int n_in,
                              void* d_out, int out_size) {
    const float* mels = (const float*)d_in[0];
    const float* w1 = (const float*)d_in[1];
    const float* w2 = (const float*)d_in[2];
    const float* w3 = (const float*)d_in[3];
    const float* w4 = (const float*)d_in[4];
    const float* w5 = (const float*)d_in[5];
    const float* w6 = (const float*)d_in[6];
    const float* b6 = (const float*)d_in[7];
    const float* bng = (const float*)d_in[8];
    const float* bnb = (const float*)d_in[9];
    const float* bnm = (const float*)d_in[10];
    const float* bnv = (const float*)d_in[11];
    const float* emb = (const float*)d_in[12];
    float* out = (float*)d_out;

    float *bufA, *w6t, *z, *enorm, *counts, *loss;
    __nv_bfloat16 *wsp, *xsA, *xsB;
    cudaGetSymbolAddress((void**)&bufA, g_bufA);
    cudaGetSymbolAddress((void**)&wsp, g_wsplit);
    cudaGetSymbolAddress((void**)&xsA, g_xsA);
    cudaGetSymbolAddress((void**)&xsB, g_xsB);
    cudaGetSymbolAddress((void**)&w6t, g_w6t);
    cudaGetSymbolAddress((void**)&z, g_z);
    cudaGetSymbolAddress((void**)&enorm, g_enorm);
    cudaGetSymbolAddress((void**)&counts, g_counts);
    cudaGetSymbolAddress((void**)&loss, g_loss);

    const int SMEM = 1024 + 2 * 6 * 8192;  // 99328
    cudaFuncSetAttribute(conv_mma_kernel<80, 3, 3, 1, 0>,
                         cudaFuncAttributeMaxDynamicSharedMemorySize, SMEM);
    cudaFuncSetAttribute(conv_mma_kernel<768, 3, 4, 2, 0>,
                         cudaFuncAttributeMaxDynamicSharedMemorySize, SMEM);
    cudaFuncSetAttribute(conv_mma_kernel<768, 4, 3, 1, 0>,
                         cudaFuncAttributeMaxDynamicSharedMemorySize, SMEM);
    cudaFuncSetAttribute(conv_mma_kernel<768, 3, 3, 1, 0>,
                         cudaFuncAttributeMaxDynamicSharedMemorySize, SMEM);
    cudaFuncSetAttribute(conv_mma_kernel<768, 3, 0, 0, 1>,
                         cudaFuncAttributeMaxDynamicSharedMemorySize, SMEM);

    auto strip = [&](__nv_bfloat16* xsbuf, int KS, int S, int PAD, int Tin,
                     int TSo) {
        int total = 3 * KS * 32 * 768 * 8;
        strip_kernel<<<(total + 255) / 256, 256>>>(xsbuf, KS, S, PAD, Tin, TSo,
                                                   total);
    };

    // Layer 1: mels -> planes(xsA) via xsplit; conv1 -> L2 planes (xsB)
    split_w_kernel<<<(768 * 256 + 255) / 256, 256>>>(w1, wsp, 80, 3, 256);
    {
        int total = 3 * 32 * 80 * (1024 / 2);
        xsplit_kernel<<<(total + 255) / 256, 256>>>(mels, xsA, 80, 1024, 1024,
                                                    1024, 1, 0, 3, total);
    }
    strip(xsB, 3, 1, 1, 1022, 1024);
    conv_mma_kernel<80, 3, 3, 1, 0><<<dim3(8, 6, 32), 256, SMEM>>>(
        xsA, wsp, bng + 0, bnb + 0, bnm + 0, bnv + 0, nullptr, xsB, 1024, 1022,
        1024);

    // Layer 2 -> L3 planes (xsA), stride-2/K4 geometry
    split_w_kernel<<<(768 * 2304 + 255) / 256, 256>>>(w2, wsp, 768, 3, 2304);
    strip(xsA, 4, 2, 1, 1022, 512);
    conv_mma_kernel<768, 3, 4, 2, 0><<<dim3(8, 6, 32), 256, SMEM>>>(
        xsB, wsp, bng + 768, bnb + 768, bnm + 768, bnv + 768, nullptr, xsA, 1024,
        1022, 512);

    // Layer 3 (K4) -> L4 planes (xsB)
    split_w_kernel<<<(768 * 3072 + 255) / 256, 256>>>(w3, wsp, 768, 4, 3072);
    strip(xsB, 3, 1, 1, 511, 512);
    conv_mma_kernel<768, 4, 3, 1, 0><<<dim3(4, 6, 32), 256, SMEM>>>(
        xsA, wsp, bng + 1536, bnb + 1536, bnm + 1536, bnv + 1536, nullptr, xsB,
        512, 511, 512);

    // Layer 4 -> L5 planes (xsA)
    split_w_kernel<<<(768 * 2304 + 255) / 256, 256>>>(w4, wsp, 768, 3, 2304);
    strip(xsA, 3, 1, 1, 511, 512);
    conv_mma_kernel<768, 3, 3, 1, 0><<<dim3(4, 6, 32), 256, SMEM>>>(
        xsB, wsp, bng + 2304, bnb + 2304, bnm + 2304, bnv + 2304, nullptr, xsA,
        512, 511, 512);

    // Layer 5 -> fp32 bufA
    split_w_kernel<<<(768 * 2304 + 255) / 256, 256>>>(w5, wsp, 768, 3, 2304);
    conv_mma_kernel<768, 3, 0, 0, 1><<<dim3(4, 6, 32), 256, SMEM>>>(
        xsA, wsp, bng + 3072, bnb + 3072, bnm + 3072, bnv + 3072, bufA, nullptr,
        512, 511, 512);

    // 1x1 conv + transpose -> z [32,511,64]
    transpose_w6_kernel<<<(768 * 64 + 255) / 256, 256>>>(w6, w6t);
    conv6_kernel<<<dim3(64, 32), 512>>>(bufA, w6t, b6, z);

    // VQ
    vq_init_kernel<<<1, 512>>>(emb, enorm, counts, loss);
    vq_kernel<<<128, 128>>>(z, emb, enorm, out, loss, counts);
    vq_final_kernel<<<1, 512>>>(counts, loss, out);
}

// round 12
// speedup vs baseline: 1.1315x; 1.1315x over previous
#include <cuda_runtime.h>
#include <cuda_bf16.h>
#include <cstdint>

// ---------------------------------------------------------------------------
// Scratch (static __device__ arrays; no allocation allowed)
// ---------------------------------------------------------------------------
__device__ float g_bufA[32u * 768u * 512u];                    // conv5 fp32 out
__device__ __nv_bfloat16 g_wsplit[3u * 768u * 3072u];          // [p][co][KPAD]
__device__ __nv_bfloat16 g_xsA[3u * 3u * 32u * 768u * 1024u];  // plane ping
__device__ __nv_bfloat16 g_xsB[3u * 3u * 32u * 768u * 1024u];  // plane pong
__device__ float g_w6t[768u * 64u];
__device__ float g_z[32u * 511u * 64u];
__device__ float g_enorm[512];
__device__ float g_counts[512];
__device__ float g_loss[1];

// ---------------------------------------------------------------------------
// Helpers (baseline PTX only — compute_103-safe)
// ---------------------------------------------------------------------------
__device__ __forceinline__ uint32_t smem_u32(const void* p) {
    uint32_t a;
    asm("{ .reg .u64 t; cvta.to.shared.u64 t, %1; cvt.u32.u64 %0, t; }"
        : "=r"(a) : "l"(p));
    return a;
}

#define LDSM4(r0, r1, r2, r3, addr)                                              \
    asm volatile("ldmatrix.sync.aligned.m8n8.x4.shared.b16 {%0,%1,%2,%3}, [%4];" \
                 : "=r"(r0), "=r"(r1), "=r"(r2), "=r"(r3) : "r"(addr))

#define LDSM4T(r0, r1, r2, r3, addr)                                             \
    asm volatile("ldmatrix.sync.aligned.m8n8.x4.trans.shared.b16 {%0,%1,%2,%3}, [%4];" \
                 : "=r"(r0), "=r"(r1), "=r"(r2), "=r"(r3) : "r"(addr))

#define MMA16816(c, a, b0, b1)                                                   \
    asm volatile(                                                                \
        "mma.sync.aligned.m16n8k16.row.col.f32.bf16.bf16.f32 "                   \
        "{%0,%1,%2,%3}, {%4,%5,%6,%7}, {%8,%9}, {%0,%1,%2,%3};"                  \
        : "+f"((c)[0]), "+f"((c)[1]), "+f"((c)[2]), "+f"((c)[3])                 \
        : "r"((a)[0]), "r"((a)[1]), "r"((a)[2]), "r"((a)[3]),                    \
          "r"(b0), "r"(b1))

#define CP_ASYNC16(dst, src, sz)                                                 \
    asm volatile("cp.async.cg.shared.global [%0], [%1], 16, %2;"                 \
                 :: "r"(dst), "l"(src), "r"(sz) : "memory")
#define CP_COMMIT() asm volatile("cp.async.commit_group;" ::: "memory")
#define CP_WAIT0() asm volatile("cp.async.wait_group 0;" ::: "memory")

__device__ __forceinline__ void split3(float v, unsigned short& h,
                                       unsigned short& m, unsigned short& l) {
    __nv_bfloat16 bh = __float2bfloat16(v);
    float fh = __bfloat162float(bh);
    __nv_bfloat16 bm = __float2bfloat16(v - fh);
    float fm = __bfloat162float(bm);
    __nv_bfloat16 bl = __float2bfloat16(v - fh - fm);
    h = __bfloat16_as_ushort(bh);
    m = __bfloat16_as_ushort(bm);
    l = __bfloat16_as_ushort(bl);
}

// ---------------------------------------------------------------------------
// Weight split: w[co][ci][tap] fp32 -> 3 bf16 planes [p][co][KPAD]
// ---------------------------------------------------------------------------
__global__ void split_w_kernel(const float* __restrict__ w,
                               __nv_bfloat16* __restrict__ w3,
                               int CIN, int KS, int KPAD) {
    int idx = blockIdx.x * 256 + threadIdx.x;
    int total = 768 * KPAD;
    if (idx >= total) return;
    int k = idx % KPAD;
    int co = idx / KPAD;
    float v = (k < CIN * KS) ? w[(size_t)co * CIN * KS + k] : 0.0f;
    unsigned short h, m, l;
    split3(v, h, m, l);
    w3[idx] = __ushort_as_bfloat16(h);
    w3[total + idx] = __ushort_as_bfloat16(m);
    w3[2 * total + idx] = __ushort_as_bfloat16(l);
}

// ---------------------------------------------------------------------------
// Activation split + tap-expand for LAYER 1 input only (mels fp32 -> planes)
// ---------------------------------------------------------------------------
__global__ void xsplit_kernel(const float* __restrict__ x,
                              __nv_bfloat16* __restrict__ xs,
                              int CIN, int T_in, int TS_in, int TSo,
                              int S, int PAD, int KS, int total) {
    int idx = blockIdx.x * 256 + threadIdx.x;
    if (idx >= total) return;
    const int th = TSo >> 1;
    int t2 = idx % th;
    int r = idx / th;
    int ci = r % CIN;
    r /= CIN;
    int bb = r & 31;
    int tap = r >> 5;
    const float* xr = x + ((size_t)bb * CIN + ci) * TS_in;

    unsigned short hb[2], mb[2], lb[2];
#pragma unroll
    for (int j = 0; j < 2; ++j) {
        int t = 2 * t2 + j;
        int tin = t * S + tap - PAD;
        float v = (tin >= 0 && tin < T_in) ? xr[tin] : 0.0f;
        split3(v, hb[j], mb[j], lb[j]);
    }
    size_t pstride = (size_t)KS * 32 * CIN * TSo;
    size_t o = (((size_t)tap * 32 + bb) * CIN + ci) * TSo + 2 * t2;
    *(uint32_t*)(xs + o) = (uint32_t)hb[0] | ((uint32_t)hb[1] << 16);
    *(uint32_t*)(xs + o + pstride) = (uint32_t)mb[0] | ((uint32_t)mb[1] << 16);
    *(uint32_t*)(xs + o + 2 * pstride) = (uint32_t)lb[0] | ((uint32_t)lb[1] << 16);
}

// ---------------------------------------------------------------------------
// Zero boundary strips of a plane buffer (slots whose source t is OOB; the
// conv epilogue never writes them). Covers first 3 / last 5 tp columns.
// Must run BEFORE the conv that writes the buffer.
// ---------------------------------------------------------------------------
__global__ void strip_kernel(__nv_bfloat16* __restrict__ xs, int KS, int S,
                             int PAD, int Tin, int TSo, int total) {
    int idx = blockIdx.x * 256 + threadIdx.x;
    if (idx >= total) return;
    int c = idx & 7;
    int r = idx >> 3;
    int ci = r % 768;
    r /= 768;
    int bb = r & 31;
    r >>= 5;
    int tap = r % KS;
    int p = r / KS;
    int tp = (c < 3) ? c : TSo - 8 + c;
    int tin = tp * S + tap - PAD;
    if (tin < 0 || tin >= Tin) {
        size_t ps = (size_t)KS * 32 * 768 * TSo;
        xs[(size_t)p * ps + (((size_t)tap * 32 + bb) * 768 + ci) * TSo + tp] =
            __ushort_as_bfloat16((unsigned short)0);
    }
}

// ---------------------------------------------------------------------------
// Conv + BN + ReLU: bf16 mma.sync, 3-way split (6 products), cp.async fill
// (mainloop identical to R8 / proven). Epilogue:
//   OUTMODE 0: stage tile in smem, then COALESCED split+tap-expand writes of
//              next layer's bf16 planes + inter-tile HALO slots (R12 fix).
//   OUTMODE 1: coalesced fp32 (for conv6 input).
// ---------------------------------------------------------------------------
template <int CIN, int KS, int NKS, int NS, int OUTMODE>
__global__ void __launch_bounds__(256, 2)
conv_mma_kernel(const __nv_bfloat16* __restrict__ xs,
                const __nv_bfloat16* __restrict__ w3,
                const float* __restrict__ gamma, const float* __restrict__ beta,
                const float* __restrict__ mean, const float* __restrict__ var,
                float* __restrict__ outf, __nv_bfloat16* __restrict__ xsn,
                int TSo, int T_out, int TSoN) {
    constexpr int KTOT = CIN * KS;
    constexpr int KPAD = ((KTOT + 31) / 32) * 32;
    constexpr int NCH = KPAD / 32;
    constexpr uint32_t BUFSZ = 6 * 8192;

    extern __shared__ __align__(16) char smem[];
    float* sInv = (float*)smem;
    float* sBb = (float*)(smem + 512);
    const uint32_t tilesBase = smem_u32(smem + 1024);

    const int b = blockIdx.z;
    const int co0 = blockIdx.y * 128;
    const int t0 = blockIdx.x * 128;
    const int tid = threadIdx.x;
    const int lane = tid & 31;
    const int warp = tid >> 5;
    const int wm = warp & 1;
    const int wn = warp >> 1;
    const int q = lane >> 3;
    const int r8 = lane & 7;

    if (tid < 128) {
        int co = co0 + tid;
        float iv = gamma[co] * rsqrtf(var[co] + 1e-5f);
        sInv[tid] = iv;
        sBb[tid] = beta[co] - mean[co] * iv;
    }

    float acc[4][4][4];
#pragma unroll
    for (int mb = 0; mb < 4; ++mb)
#pragma unroll
        for (int nb = 0; nb < 4; ++nb)
#pragma unroll
            for (int e = 0; e < 4; ++e) acc[mb][nb][e] = 0.0f;

    const size_t pstride = (size_t)KS * 32 * CIN * TSo;

    auto fill = [&](int c, uint32_t bsel) {
        const uint32_t tb = tilesBase + bsel * BUFSZ;
        // A: 3 planes x 128 rows x 4 x 16B
#pragma unroll
        for (int i = 0; i < 6; ++i) {
            int task = tid + i * 256;
            int g = task & 3;
            int row = (task >> 2) & 127;
            int p = task >> 9;
            uint32_t dst = tb + p * 8192 + (row << 6) + (((g + (row >> 1)) & 3) << 4);
            const __nv_bfloat16* src =
                w3 + ((size_t)(p * 768 + co0 + row)) * KPAD + c * 32 + g * 8;
            CP_ASYNC16(dst, src, 16);
        }
        // B: 3 planes x 32 k x 16 x 16B
#pragma unroll
        for (int i = 0; i < 6; ++i) {
            int task = tid + i * 256;
            int tg = task & 15;
            int k = (task >> 4) & 31;
            int p = task >> 9;
            int kg = c * 32 + k;
            int ci = kg / KS;
            int tap = kg - ci * KS;
            const __nv_bfloat16* src =
                xs + (size_t)p * pstride +
                (((size_t)tap * 32 + b) * CIN + ci) * TSo + t0 + tg * 8;
            uint32_t dst = tb + 24576 + p * 8192 + (k << 8) + ((tg ^ (k & 7)) << 4);
            int sz = (kg < KTOT) ? 16 : 0;
            CP_ASYNC16(dst, src, sz);
        }
        CP_COMMIT();
    };

    fill(0, 0);

#pragma unroll 1
    for (int c = 0; c < NCH; ++c) {
        CP_WAIT0();
        __syncthreads();
        if (c + 1 < NCH) fill(c + 1, (c + 1) & 1);
        const uint32_t tb = tilesBase + (uint32_t)(c & 1) * BUFSZ;

#pragma unroll
        for (int ks = 0; ks < 2; ++ks) {
            uint32_t bfr[3][4][2];
#pragma unroll
            for (int p = 0; p < 3; ++p) {
#pragma unroll
                for (int jj = 0; jj < 2; ++jj) {
                    uint32_t k = ks * 16 + (q & 1) * 8 + r8;
                    uint32_t tg = wn * 4 + 2 * jj + (q >> 1);
                    uint32_t ad = tb + 24576 + p * 8192 + (k << 8) +
                                  ((tg ^ (k & 7)) << 4);
                    LDSM4T(bfr[p][2 * jj][0], bfr[p][2 * jj][1],
                           bfr[p][2 * jj + 1][0], bfr[p][2 * jj + 1][1], ad);
                }
            }
#pragma unroll
            for (int pa = 0; pa < 3; ++pa) {
                uint32_t a[4][4];
#pragma unroll
                for (int mb = 0; mb < 4; ++mb) {
                    uint32_t row = wm * 64 + mb * 16 + (q & 1) * 8 + r8;
                    uint32_t g = ks * 2 + (q >> 1);
                    uint32_t ad = tb + pa * 8192 + (row << 6) +
                                  (((g + (row >> 1)) & 3) << 4);
                    LDSM4(a[mb][0], a[mb][1], a[mb][2], a[mb][3], ad);
                }
#pragma unroll
                for (int pb = 0; pb < 3 - pa; ++pb)
#pragma unroll
                    for (int mb = 0; mb < 4; ++mb)
#pragma unroll
                        for (int nb = 0; nb < 4; ++nb)
                            MMA16816(acc[mb][nb], a[mb], bfr[pb][nb][0],
                                     bfr[pb][nb][1]);
            }
        }
    }

    // ---- Epilogue phase 1: stage BN+ReLU'd tile into smem [128][132] fp32 ----
    __syncthreads();
    float* sy = (float*)(smem + 1024);
    {
        const int colb_l = wn * 32 + (lane & 3) * 2;
#pragma unroll
        for (int mb = 0; mb < 4; ++mb) {
            const int row0 = wm * 64 + mb * 16 + (lane >> 2);
            const float i0 = sInv[row0], b0 = sBb[row0];
            const float i1 = sInv[row0 + 8], b1 = sBb[row0 + 8];
#pragma unroll
            for (int nb = 0; nb < 4; ++nb) {
                int cl = colb_l + nb * 8;
                float2 v0, v1;
                v0.x = fmaxf(acc[mb][nb][0] * i0 + b0, 0.0f);
                v0.y = fmaxf(acc[mb][nb][1] * i0 + b0, 0.0f);
                v1.x = fmaxf(acc[mb][nb][2] * i1 + b1, 0.0f);
                v1.y = fmaxf(acc[mb][nb][3] * i1 + b1, 0.0f);
                *(float2*)&sy[row0 * 132 + cl] = v0;
                *(float2*)&sy[(row0 + 8) * 132 + cl] = v1;
            }
        }
    }
    __syncthreads();

    // ---- Epilogue phase 2: coalesced writes (+ inter-tile halo slots) ----
    if (OUTMODE == 1) {
#pragma unroll 1
        for (int rr = 0; rr < 16; ++rr) {
            int row = warp * 16 + rr;
            float4 v = *(float4*)&sy[row * 132 + lane * 4];
            *(float4*)&outf[((size_t)b * 768 + co0 + row) * TSo + t0 + lane * 4] = v;
        }
    } else {
        unsigned short* xp = (unsigned short*)xsn;
        const size_t psN = (size_t)NKS * 32 * 768 * TSoN;
#pragma unroll 1
        for (int rr = 0; rr < 16; ++rr) {
            const int row = warp * 16 + rr;
            const int r0g = co0 + row;
            unsigned short hh[6], hm[6], hl[6];
#pragma unroll
            for (int u = 0; u < 6; ++u) {
                int lt = 4 * lane - 1 + u;
                float v = (lt >= 0 && lt < 128) ? sy[row * 132 + lt] : 0.0f;
                split3(v, hh[u], hm[u], hl[u]);
            }
            if (NS == 1) {
                const int tp0 = t0 + 4 * lane;
#pragma unroll
                for (int tap = 0; tap < NKS; ++tap) {
                    size_t o = (((size_t)tap * 32 + b) * 768 + r0g) * TSoN + tp0;
                    int lo = 4 * lane + tap - 1;  // source lt for j=0
                    bool fast = (lo >= 0) && (lo + 3 < 128) && (t0 + lo + 3 < T_out);
                    if (fast) {
                        ushort4 vh = make_ushort4(hh[tap], hh[tap + 1],
                                                  hh[tap + 2], hh[tap + 3]);
                        ushort4 vm = make_ushort4(hm[tap], hm[tap + 1],
                                                  hm[tap + 2], hm[tap + 3]);
                        ushort4 vl = make_ushort4(hl[tap], hl[tap + 1],
                                                  hl[tap + 2], hl[tap + 3]);
                        *(ushort4*)(xp + o) = vh;
                        *(ushort4*)(xp + o + psN) = vm;
                        *(ushort4*)(xp + o + 2 * psN) = vl;
                    } else {
#pragma unroll
                        for (int j = 0; j < 4; ++j) {
                            int lt = lo + j;
                            if (lt >= 0 && lt < 128 && t0 + lt < T_out) {
                                xp[o + j] = hh[tap + j];
                                xp[o + j + psN] = hm[tap + j];
                                xp[o + j + 2 * psN] = hl[tap + j];
                            }
                        }
                    }
                }
                // HALO: slot (tap=2, tp=t0-1) sources y[t0] (ours, lane 0);
                //       slot (tap=0, tp=t0+128) sources y[t0+127] (ours, lane 31)
                if (lane == 0 && t0 > 0) {
                    size_t o = (((size_t)2 * 32 + b) * 768 + r0g) * TSoN + (t0 - 1);
                    xp[o] = hh[1];
                    xp[o + psN] = hm[1];
                    xp[o + 2 * psN] = hl[1];
                }
                if (lane == 31 && t0 + 128 < TSoN && t0 + 127 < T_out) {
                    size_t o = ((size_t)b * 768 + r0g) * TSoN + (t0 + 128);
                    xp[o] = hh[4];
                    xp[o + psN] = hm[4];
                    xp[o + 2 * psN] = hl[4];
                }
            } else {  // NS == 2 (NKS == 4)
                const int tp0 = (t0 >> 1) + 2 * lane;
#pragma unroll
                for (int tap = 0; tap < NKS; ++tap) {
                    size_t o = (((size_t)tap * 32 + b) * 768 + r0g) * TSoN + tp0;
                    int lo = 4 * lane + tap - 1;  // source lt for j=0 (j step 2)
                    bool fast = (lo >= 0) && (lo + 2 < 128) && (t0 + lo + 2 < T_out);
                    if (fast) {
                        *(ushort2*)(xp + o) = make_ushort2(hh[tap], hh[tap + 2]);
                        *(ushort2*)(xp + o + psN) =
                            make_ushort2(hm[tap], hm[tap + 2]);
                        *(ushort2*)(xp + o + 2 * psN) =
                            make_ushort2(hl[tap], hl[tap + 2]);
                    } else {
#pragma unroll
                        for (int j = 0; j < 2; ++j) {
                            int lt = lo + 2 * j;
                            if (lt >= 0 && lt < 128 && t0 + lt < T_out) {
                                xp[o + j] = hh[tap + 2 * j];
                                xp[o + j + psN] = hm[tap + 2 * j];
                                xp[o + j + 2 * psN] = hl[tap + 2 * j];
                            }
                        }
                    }
                }
                // HALO: slot (tap=3, tp=t0/2-1) sources y[t0] (lane 0);
                //       slot (tap=0, tp=t0/2+64) sources y[t0+127] (lane 31)
                if (lane == 0 && t0 > 0) {
                    size_t o =
                        (((size_t)3 * 32 + b) * 768 + r0g) * TSoN + ((t0 >> 1) - 1);
                    xp[o] = hh[1];
                    xp[o + psN] = hm[1];
                    xp[o + 2 * psN] = hl[1];
                }
                if (lane == 31 && (t0 >> 1) + 64 < TSoN && t0 + 127 < T_out) {
                    size_t o = ((size_t)b * 768 + r0g) * TSoN + ((t0 >> 1) + 64);
                    xp[o] = hh[4];
                    xp[o + psN] = hm[4];
                    xp[o + 2 * psN] = hl[4];
                }
            }
        }
    }
}

// ---------------------------------------------------------------------------
// 1x1 conv (w6) + bias + transpose to [B][T'][D]
// ---------------------------------------------------------------------------
__global__ void transpose_w6_kernel(const float* __restrict__ w6,
                                    float* __restrict__ w6t) {
    int idx = blockIdx.x * 256 + threadIdx.x;
    if (idx >= 768 * 64) return;
    int d = idx & 63;
    int ci = idx >> 6;
    w6t[idx] = w6[(size_t)d * 768 + ci];
}

__global__ void conv6_kernel(const float* __restrict__ x,
                             const float* __restrict__ w6t,
                             const float* __restrict__ b6,
                             float* __restrict__ z) {
    __shared__ float xsm[8][768];
    __shared__ float ws[64][64];
    const int b = blockIdx.y;
    const int t0 = blockIdx.x * 8;
    const int tid = threadIdx.x;

    for (int idx = tid; idx < 8 * 768; idx += 512) {
        int ci = idx >> 3, tl = idx & 7;
        int t = t0 + tl;
        xsm[tl][ci] = (t < 511) ? x[((size_t)b * 768 + ci) * 512 + t] : 0.0f;
    }
    const int tl = tid >> 6;
    const int d = tid & 63;
    float acc = 0.0f;
    for (int c0 = 0; c0 < 768; c0 += 64) {
        __syncthreads();
        for (int idx = tid; idx < 64 * 64; idx += 512) {
            int cc = idx >> 6, dd = idx & 63;
            ws[cc][dd] = w6t[(size_t)(c0 + cc) * 64 + dd];
        }
        __syncthreads();
#pragma unroll
        for (int cc = 0; cc < 64; ++cc) acc = fmaf(xsm[tl][c0 + cc], ws[cc][d], acc);
    }
    int t = t0 + tl;
    if (t < 511) z[((size_t)b * 511 + t) * 64 + d] = acc + b6[d];
}

// ---------------------------------------------------------------------------
// VQ
// ---------------------------------------------------------------------------
__global__ void vq_init_kernel(const float* __restrict__ emb,
                               float* __restrict__ enorm,
                               float* __restrict__ counts,
                               float* __restrict__ loss) {
    int c = threadIdx.x;
    float s = 0.0f;
#pragma unroll
    for (int dd = 0; dd < 64; ++dd) {
        float e = emb[(size_t)c * 64 + dd];
        s = fmaf(e, e, s);
    }
    enorm[c] = s;
    counts[c] = 0.0f;
    if (c == 0) loss[0] = 0.0f;
}

__global__ void vq_kernel(const float* __restrict__ z,
                          const float* __restrict__ emb,
                          const float* __restrict__ enorm,
                          float* __restrict__ out,
                          float* __restrict__ loss,
                          float* __restrict__ counts) {
    __shared__ __align__(16) float sE[128 * 64];
    __shared__ float sN[128];
    __shared__ float red[128];
    const int tid = threadIdx.x;
    const int row = blockIdx.x * 128 + tid;
    const bool valid = row < 16352;

    float zr[64];
    if (valid) {
#pragma unroll
        for (int k = 0; k < 16; ++k)
            *(float4*)&zr[k * 4] = *(const float4*)&z[(size_t)row * 64 + k * 4];
    } else {
#pragma unroll
        for (int k = 0; k < 64; ++k) zr[k] = 0.0f;
    }

    float best = 3.4e38f;
    int bi = 0;
    for (int c0 = 0; c0 < 512; c0 += 128) {
        __syncthreads();
        for (int k = tid; k < 2048; k += 128)
            ((float4*)sE)[k] = ((const float4*)(emb + (size_t)c0 * 64))[k];
        sN[tid] = enorm[c0 + tid];
        __syncthreads();
        const float4* sE4 = (const float4*)sE;
        for (int c = 0; c < 128; ++c) {
            float d0 = 0.0f, d1 = 0.0f, d2 = 0.0f, d3 = 0.0f;
#pragma unroll
            for (int k = 0; k < 16; ++k) {
                float4 e = sE4[c * 16 + k];
                d0 = fmaf(zr[4 * k + 0], e.x, d0);
                d1 = fmaf(zr[4 * k + 1], e.y, d1);
                d2 = fmaf(zr[4 * k + 2], e.z, d2);
                d3 = fmaf(zr[4 * k + 3], e.w, d3);
            }
            float dot = (d0 + d1) + (d2 + d3);
            float dist = fmaf(-2.0f, dot, sN[c]);
            if (dist < best) { best = dist; bi = c0 + c; }
        }
    }

    float diff2 = 0.0f;
    if (valid) {
        const float* e = emb + (size_t)bi * 64;
#pragma unroll
        for (int dd = 0; dd < 64; ++dd) {
            float ev = e[dd];
            out[(size_t)row * 64 + dd] = ev;
            float df = zr[dd] - ev;
            diff2 = fmaf(df, df, diff2);
        }
        atomicAdd(&counts[bi], 1.0f);
    }
    red[tid] = diff2;
    __syncthreads();
    for (int s = 64; s > 0; s >>= 1) {
        if (tid < s) red[tid] += red[tid + s];
        __syncthreads();
    }
    if (tid == 0) atomicAdd(loss, red[0]);
}

__global__ void vq_final_kernel(const float* __restrict__ counts,
                                const float* __restrict__ loss,
                                float* __restrict__ out) {
    __shared__ float red[512];
    int tid = threadIdx.x;
    float avg = counts[tid] * (1.0f / 16352.0f);
    red[tid] = avg * logf(avg + 1e-10f);
    __syncthreads();
    for (int s = 256; s > 0; s >>= 1) {
        if (tid < s) red[tid] += red[tid + s];
        __syncthreads();
    }
    if (tid == 0) {
        out[1046528] = 0.25f * loss[0] * (1.0f / 1046528.0f);
        out[1046529] = expf(-red[0]);
    }
}

// ---------------------------------------------------------------------------
// kernel_launch
// ---------------------------------------------------------------------------
extern "C" void kernel_launch(void* const* d_in, const int* in_sizes, int n_in,
                              void* d_out, int out_size) {
    const float* mels = (const float*)d_in[0];
    const float* w1 = (const float*)d_in[1];
    const float* w2 = (const float*)d_in[2];
    const float* w3 = (const float*)d_in[3];
    const float* w4 = (const float*)d_in[4];
    const float* w5 = (const float*)d_in[5];
    const float* w6 = (const float*)d_in[6];
    const float* b6 = (const float*)d_in[7];
    const float* bng = (const float*)d_in[8];
    const float* bnb = (const float*)d_in[9];
    const float* bnm = (const float*)d_in[10];
    const float* bnv = (const float*)d_in[11];
    const float* emb = (const float*)d_in[12];
    float* out = (float*)d_out;

    float *bufA, *w6t, *z, *enorm, *counts, *loss;
    __nv_bfloat16 *wsp, *xsA, *xsB;
    cudaGetSymbolAddress((void**)&bufA, g_bufA);
    cudaGetSymbolAddress((void**)&wsp, g_wsplit);
    cudaGetSymbolAddress((void**)&xsA, g_xsA);
    cudaGetSymbolAddress((void**)&xsB, g_xsB);
    cudaGetSymbolAddress((void**)&w6t, g_w6t);
    cudaGetSymbolAddress((void**)&z, g_z);
    cudaGetSymbolAddress((void**)&enorm, g_enorm);
    cudaGetSymbolAddress((void**)&counts, g_counts);
    cudaGetSymbolAddress((void**)&loss, g_loss);

    const int SMEM = 1024 + 2 * 6 * 8192;  // 99328
    cudaFuncSetAttribute(conv_mma_kernel<80, 3, 3, 1, 0>,
                         cudaFuncAttributeMaxDynamicSharedMemorySize, SMEM);
    cudaFuncSetAttribute(conv_mma_kernel<768, 3, 4, 2, 0>,
                         cudaFuncAttributeMaxDynamicSharedMemorySize, SMEM);
    cudaFuncSetAttribute(conv_mma_kernel<768, 4, 3, 1, 0>,
                         cudaFuncAttributeMaxDynamicSharedMemorySize, SMEM);
    cudaFuncSetAttribute(conv_mma_kernel<768, 3, 3, 1, 0>,
                         cudaFuncAttributeMaxDynamicSharedMemorySize, SMEM);
    cudaFuncSetAttribute(conv_mma_kernel<768, 3, 0, 1, 1>,
                         cudaFuncAttributeMaxDynamicSharedMemorySize, SMEM);

    auto strip = [&](__nv_bfloat16* xsbuf, int KS, int S, int PAD, int Tin,
                     int TSo) {
        int total = 3 * KS * 32 * 768 * 8;
        strip_kernel<<<(total + 255) / 256, 256>>>(xsbuf, KS, S, PAD, Tin, TSo,
                                                   total);
    };

    // Layer 1: mels -> planes(xsA) via xsplit; conv1 -> L2 planes (xsB)
    split_w_kernel<<<(768 * 256 + 255) / 256, 256>>>(w1, wsp, 80, 3, 256);
    {
        int total = 3 * 32 * 80 * (1024 / 2);
        xsplit_kernel<<<(total + 255) / 256, 256>>>(mels, xsA, 80, 1024, 1024,
                                                    1024, 1, 0, 3, total);
    }
    strip(xsB, 3, 1, 1, 1022, 1024);
    conv_mma_kernel<80, 3, 3, 1, 0><<<dim3(8, 6, 32), 256, SMEM>>>(
        xsA, wsp, bng + 0, bnb + 0, bnm + 0, bnv + 0, nullptr, xsB, 1024, 1022,
        1024);

    // Layer 2 -> L3 planes (xsA): next geometry K4/S2, TSoN=512
    split_w_kernel<<<(768 * 2304 + 255) / 256, 256>>>(w2, wsp, 768, 3, 2304);
    strip(xsA, 4, 2, 1, 1022, 512);
    conv_mma_kernel<768, 3, 4, 2, 0><<<dim3(8, 6, 32), 256, SMEM>>>(
        xsB, wsp, bng + 768, bnb + 768, bnm + 768, bnv + 768, nullptr, xsA, 1024,
        1022, 512);

    // Layer 3 (K4, input planes TSo=512) -> L4 planes (xsB)
    split_w_kernel<<<(768 * 3072 + 255) / 256, 256>>>(w3, wsp, 768, 4, 3072);
    strip(xsB, 3, 1, 1, 511, 512);
    conv_mma_kernel<768, 4, 3, 1, 0><<<dim3(4, 6, 32), 256, SMEM>>>(
        xsA, wsp, bng + 1536, bnb + 1536, bnm + 1536, bnv + 1536, nullptr, xsB,
        512, 511, 512);

    // Layer 4 -> L5 planes (xsA)
    split_w_kernel<<<(768 * 2304 + 255) / 256, 256>>>(w4, wsp, 768, 3, 2304);
    strip(xsA, 3, 1, 1, 511, 512);
    conv_mma_kernel<768, 3, 3, 1, 0><<<dim3(4, 6, 32), 256, SMEM>>>(
        xsB, wsp, bng + 2304, bnb + 2304, bnm + 2304, bnv + 2304, nullptr, xsA,
        512, 511, 512);

    // Layer 5 -> fp32 bufA (coalesced float4 epilogue)
    split_w_kernel<<<(768 * 2304 + 255) / 256, 256>>>(w5, wsp, 768, 3, 2304);
    conv_mma_kernel<768, 3, 0, 1, 1><<<dim3(4, 6, 32), 256, SMEM>>>(
        xsA, wsp, bng + 3072, bnb + 3072, bnm + 3072, bnv + 3072, bufA, nullptr,
        512, 511, 512);

    // 1x1 conv + transpose -> z [32,511,64]
    transpose_w6_kernel<<<(768 * 64 + 255) / 256, 256>>>(w6, w6t);
    conv6_kernel<<<dim3(64, 32), 512>>>(bufA, w6t, b6, z);

    // VQ
    vq_init_kernel<<<1, 512>>>(emb, enorm, counts, loss);
    vq_kernel<<<128, 128>>>(z, emb, enorm, out, loss, counts);
    vq_final_kernel<<<1, 512>>>(counts, loss, out);
}